// round 5
// baseline (speedup 1.0000x reference)
#include <cuda_runtime.h>
#include <cuda_bf16.h>

// Problem constants
#define B_    2048
#define CELL_ 512
#define K_    30
#define L_    1024
#define V_    80
#define P_    90      // 3*K
#define NWARP 8
#define THREADS (NWARP*32)   // 256

__global__ __launch_bounds__(THREADS, 4)
void window_kernel(const float* __restrict__ x,
                   const float* __restrict__ kappa_old,
                   const float* __restrict__ oh,
                   const float* __restrict__ tlen,
                   const float* __restrict__ W,
                   const float* __restrict__ bias,
                   float* __restrict__ out)
{
    const int b    = blockIdx.x;
    const int tid  = threadIdx.x;
    const int lane = tid & 31;
    const int warp = tid >> 5;

    __shared__ float  xs[CELL_];
    __shared__ float  alpha_s[K_], beta_s[K_], kappa_s[K_];
    __shared__ float  phi_s[L_ + 1];
    __shared__ float4 red4[NWARP * 160];   // 20 KB staging for final reduction

    // ---- load x row into smem (vectorized) ----
    {
        const float4* xrow4 = (const float4*)(x + (size_t)b * CELL_);
        float4* xs4 = (float4*)xs;
        for (int i = tid; i < CELL_ / 4; i += THREADS) xs4[i] = xrow4[i];
    }
    __syncthreads();

    // ---- params = exp(x @ W.T + bias); warp w handles p = w, w+8, ... ----
    for (int p = warp; p < P_; p += NWARP) {
        const float4* Wr4 = (const float4*)(W + (size_t)p * CELL_);
        const float4* xs4 = (const float4*)xs;
        float s = 0.f;
        #pragma unroll
        for (int c = lane; c < CELL_ / 4; c += 32) {
            float4 wv = Wr4[c];
            float4 xv = xs4[c];
            s += wv.x * xv.x + wv.y * xv.y + wv.z * xv.z + wv.w * xv.w;
        }
        #pragma unroll
        for (int o = 16; o; o >>= 1) s += __shfl_xor_sync(0xffffffffu, s, o);
        if (lane == 0) {
            float v = __expf(s + bias[p]);
            if (p < K_) {
                alpha_s[p] = v;
            } else if (p < 2 * K_) {
                beta_s[p - K_] = v;
            } else {
                int kk = p - 2 * K_;
                float kap = kappa_old[(size_t)b * K_ + kk] + v;
                kappa_s[kk] = kap;
                out[(size_t)B_ * V_ + (size_t)b * K_ + kk] = kap;  // kappa output
            }
        }
    }
    __syncthreads();

    // ---- phi[l] = scale * sum_k alpha_k * exp(-beta_k*(kappa_k - l)^2) ----
    const float scale = (float)L_ / tlen[b];
    float* phi_out = out + (size_t)B_ * V_ + (size_t)B_ * K_ + (size_t)b * (L_ + 1);
    for (int l = tid; l <= L_; l += THREADS) {
        const float fl = (float)l;
        float s = 0.f;
        #pragma unroll
        for (int k = 0; k < K_; k++) {
            float d = kappa_s[k] - fl;
            s += alpha_s[k] * __expf(-beta_s[k] * d * d);
        }
        s *= scale;
        phi_s[l]   = s;
        phi_out[l] = s;
    }
    __syncthreads();

    // ---- w[v] = sum_{l<L} phi[l] * oh[b][l][v] ----
    // One row = 80 floats = 20 float4. Each warp handles 8 rows (=160 float4)
    // per iteration; ALL 32 lanes load 5 float4 each at flat index lane+32j
    // (coalesced LDG.128 with immediate offsets, streaming hint). Each (lane,j)
    // has a FIXED row-offset r_j=(lane+32j)/20 and column-group c_j=(lane+32j)%20,
    // so accumulation stays in 5 float4 registers; no atomics needed.
    {
        // fixed per-thread constants
        int rj[5], fj[5];
        #pragma unroll
        for (int j = 0; j < 5; j++) {
            fj[j] = lane + 32 * j;      // within-warp flat float4 index [0,160)
            rj[j] = fj[j] / 20;         // row offset within the warp's 8-row group
        }

        const float4* p = (const float4*)(oh + (size_t)b * L_ * V_) + warp * 160 + lane;
        float4 acc[5];
        #pragma unroll
        for (int j = 0; j < 5; j++) acc[j] = make_float4(0.f, 0.f, 0.f, 0.f);

        int rowbase = warp * 8;
        // 1024 rows / (8 warps * 8 rows) = 16 iterations
        #pragma unroll 2
        for (int it = 0; it < 16; ++it) {
            float4 r[5];
            #pragma unroll
            for (int j = 0; j < 5; j++) r[j] = __ldcs(&p[32 * j]);
            #pragma unroll
            for (int j = 0; j < 5; j++) {
                float ph = phi_s[rowbase + rj[j]];
                acc[j].x += ph * r[j].x;
                acc[j].y += ph * r[j].y;
                acc[j].z += ph * r[j].z;
                acc[j].w += ph * r[j].w;
            }
            p += 1280;          // 64 rows * 20 float4
            rowbase += 64;
        }

        #pragma unroll
        for (int j = 0; j < 5; j++) red4[warp * 160 + fj[j]] = acc[j];
    }
    __syncthreads();

    // final reduction: thread v (<80) sums its column across 8 warps x 8 row-offsets
    if (tid < V_) {
        const int v4 = tid >> 2;        // column group 0..19
        const int c  = tid & 3;         // component within float4
        const float* rf = (const float*)red4;
        float s = 0.f;
        #pragma unroll
        for (int w2 = 0; w2 < NWARP; w2++) {
            #pragma unroll
            for (int i = 0; i < 8; i++) {
                s += rf[(w2 * 160 + v4 + 20 * i) * 4 + c];
            }
        }
        out[(size_t)b * V_ + tid] = s;   // w output
    }
}

extern "C" void kernel_launch(void* const* d_in, const int* in_sizes, int n_in,
                              void* d_out, int out_size)
{
    const float* x         = (const float*)d_in[0];   // [B, CELL]
    const float* kappa_old = (const float*)d_in[1];   // [B, K]
    const float* oh        = (const float*)d_in[2];   // [B, L, V]
    const float* tlen      = (const float*)d_in[3];   // [B, 1]
    const float* W         = (const float*)d_in[4];   // [3K, CELL]
    const float* bias      = (const float*)d_in[5];   // [3K]
    float* out             = (float*)d_out;           // [B*V | B*K | B*(L+1)]

    window_kernel<<<B_, THREADS>>>(x, kappa_old, oh, tlen, W, bias, out);
}

// round 7
// speedup vs baseline: 1.0078x; 1.0078x over previous
#include <cuda_runtime.h>
#include <cuda_bf16.h>

// Problem constants
#define B_    2048
#define CELL_ 512
#define K_    30
#define L_    1024
#define V_    80
#define P_    90      // 3*K
#define NWARP 8
#define THREADS (NWARP*32)   // 256

__global__ __launch_bounds__(THREADS, 8)
void window_kernel(const float* __restrict__ x,
                   const float* __restrict__ kappa_old,
                   const float* __restrict__ oh,
                   const float* __restrict__ tlen,
                   const float* __restrict__ W,
                   const float* __restrict__ bias,
                   float* __restrict__ out)
{
    const int b    = blockIdx.x;
    const int tid  = threadIdx.x;
    const int lane = tid & 31;
    const int warp = tid >> 5;

    __shared__ float  xs[CELL_];
    __shared__ float  alpha_s[K_], beta_s[K_], kappa_s[K_];
    __shared__ float  phi_s[L_ + 1];
    __shared__ float4 red[NWARP * 20];   // 8 warps x 20 float4 = 2.56 KB

    // ---- load x row into smem (vectorized) ----
    {
        const float4* xrow4 = (const float4*)(x + (size_t)b * CELL_);
        float4* xs4 = (float4*)xs;
        for (int i = tid; i < CELL_ / 4; i += THREADS) xs4[i] = xrow4[i];
    }
    __syncthreads();

    // ---- params = exp(x @ W.T + bias); warp w handles p = w, w+8, ... ----
    for (int p = warp; p < P_; p += NWARP) {
        const float4* Wr4 = (const float4*)(W + (size_t)p * CELL_);
        const float4* xs4 = (const float4*)xs;
        float s = 0.f;
        #pragma unroll
        for (int c = lane; c < CELL_ / 4; c += 32) {
            float4 wv = Wr4[c];
            float4 xv = xs4[c];
            s += wv.x * xv.x + wv.y * xv.y + wv.z * xv.z + wv.w * xv.w;
        }
        #pragma unroll
        for (int o = 16; o; o >>= 1) s += __shfl_xor_sync(0xffffffffu, s, o);
        if (lane == 0) {
            float v = __expf(s + bias[p]);
            if (p < K_) {
                alpha_s[p] = v;
            } else if (p < 2 * K_) {
                beta_s[p - K_] = v;
            } else {
                int kk = p - 2 * K_;
                float kap = kappa_old[(size_t)b * K_ + kk] + v;
                kappa_s[kk] = kap;
                out[(size_t)B_ * V_ + (size_t)b * K_ + kk] = kap;  // kappa output
            }
        }
    }
    __syncthreads();

    // ---- phi[l] = scale * sum_k alpha_k * exp(-beta_k*(kappa_k - l)^2) ----
    const float scale = (float)L_ / tlen[b];
    float* phi_out = out + (size_t)B_ * V_ + (size_t)B_ * K_ + (size_t)b * (L_ + 1);
    for (int l = tid; l <= L_; l += THREADS) {
        const float fl = (float)l;
        float s = 0.f;
        #pragma unroll
        for (int k = 0; k < K_; k++) {
            float d = kappa_s[k] - fl;
            s += alpha_s[k] * __expf(-beta_s[k] * d * d);
        }
        s *= scale;
        phi_s[l]   = s;
        phi_out[l] = s;
    }
    __syncthreads();

    // ---- w[v] = sum_{l<L} phi[l] * oh[b][l][v] ----
    // One row = 80 floats = 20 float4 (16B aligned). Lanes 0..19 of each warp
    // fetch a whole row as LDG.128; warp-strided over l, unrolled x4 with
    // front-batched independent loads for MLP. ~28 live regs -> fits the
    // 32-reg cap needed for 8 CTAs/SM (64 warps).
    if (lane < 20) {
        const float4* base = (const float4*)(oh + (size_t)b * L_ * V_) + lane;
        float4 acc = make_float4(0.f, 0.f, 0.f, 0.f);
        // 1024 / (8 warps * 4 unroll) = 32 iterations, no remainder
        for (int l0 = warp; l0 < L_; l0 += NWARP * 4) {
            float4 r0 = base[(size_t)(l0            ) * 20];
            float4 r1 = base[(size_t)(l0 +     NWARP) * 20];
            float4 r2 = base[(size_t)(l0 + 2 * NWARP) * 20];
            float4 r3 = base[(size_t)(l0 + 3 * NWARP) * 20];
            float p0 = phi_s[l0];
            float p1 = phi_s[l0 +     NWARP];
            float p2 = phi_s[l0 + 2 * NWARP];
            float p3 = phi_s[l0 + 3 * NWARP];
            acc.x += p0 * r0.x; acc.y += p0 * r0.y; acc.z += p0 * r0.z; acc.w += p0 * r0.w;
            acc.x += p1 * r1.x; acc.y += p1 * r1.y; acc.z += p1 * r1.z; acc.w += p1 * r1.w;
            acc.x += p2 * r2.x; acc.y += p2 * r2.y; acc.z += p2 * r2.z; acc.w += p2 * r2.w;
            acc.x += p3 * r3.x; acc.y += p3 * r3.y; acc.z += p3 * r3.z; acc.w += p3 * r3.w;
        }
        red[warp * 20 + lane] = acc;
    }
    __syncthreads();

    // final cross-warp reduction: thread v (<80) sums scalar slot v of all warps
    if (tid < V_) {
        const float* red_f = (const float*)red;
        float s = 0.f;
        #pragma unroll
        for (int w2 = 0; w2 < NWARP; w2++) s += red_f[w2 * V_ + tid];
        out[(size_t)b * V_ + tid] = s;   // w output
    }
}

extern "C" void kernel_launch(void* const* d_in, const int* in_sizes, int n_in,
                              void* d_out, int out_size)
{
    const float* x         = (const float*)d_in[0];   // [B, CELL]
    const float* kappa_old = (const float*)d_in[1];   // [B, K]
    const float* oh        = (const float*)d_in[2];   // [B, L, V]
    const float* tlen      = (const float*)d_in[3];   // [B, 1]
    const float* W         = (const float*)d_in[4];   // [3K, CELL]
    const float* bias      = (const float*)d_in[5];   // [3K]
    float* out             = (float*)d_out;           // [B*V | B*K | B*(L+1)]

    window_kernel<<<B_, THREADS>>>(x, kappa_old, oh, tlen, W, bias, out);
}

// round 11
// speedup vs baseline: 1.3646x; 1.3541x over previous
#include <cuda_runtime.h>
#include <cuda_bf16.h>

// Problem constants
#define B_    2048
#define CELL_ 512
#define K_    30
#define L_    1024
#define V_    80
#define P_    90      // 3*K
#define NWARP 8
#define THREADS (NWARP*32)   // 256

// ============================================================================
// Kernel A: params = exp(x@W.T + b); kappa; phi  (compute-heavy, reg-hungry)
// ============================================================================
__global__ __launch_bounds__(THREADS)
void params_phi_kernel(const float* __restrict__ x,
                       const float* __restrict__ kappa_old,
                       const float* __restrict__ tlen,
                       const float* __restrict__ W,
                       const float* __restrict__ bias,
                       float* __restrict__ out)
{
    const int b    = blockIdx.x;
    const int tid  = threadIdx.x;
    const int lane = tid & 31;
    const int warp = tid >> 5;

    __shared__ float xs[CELL_];
    __shared__ float alpha_s[K_], beta_s[K_], kappa_s[K_];

    // ---- load x row into smem (vectorized) ----
    {
        const float4* xrow4 = (const float4*)(x + (size_t)b * CELL_);
        float4* xs4 = (float4*)xs;
        for (int i = tid; i < CELL_ / 4; i += THREADS) xs4[i] = xrow4[i];
    }
    __syncthreads();

    // ---- params; warp w handles p = w, w+8, ... ----
    for (int p = warp; p < P_; p += NWARP) {
        const float4* Wr4 = (const float4*)(W + (size_t)p * CELL_);
        const float4* xs4 = (const float4*)xs;
        float s = 0.f;
        #pragma unroll
        for (int c = lane; c < CELL_ / 4; c += 32) {
            float4 wv = Wr4[c];
            float4 xv = xs4[c];
            s += wv.x * xv.x + wv.y * xv.y + wv.z * xv.z + wv.w * xv.w;
        }
        #pragma unroll
        for (int o = 16; o; o >>= 1) s += __shfl_xor_sync(0xffffffffu, s, o);
        if (lane == 0) {
            float v = __expf(s + bias[p]);
            if (p < K_) {
                alpha_s[p] = v;
            } else if (p < 2 * K_) {
                beta_s[p - K_] = v;
            } else {
                int kk = p - 2 * K_;
                float kap = kappa_old[(size_t)b * K_ + kk] + v;
                kappa_s[kk] = kap;
                out[(size_t)B_ * V_ + (size_t)b * K_ + kk] = kap;  // kappa output
            }
        }
    }
    __syncthreads();

    // ---- phi[l] = scale * sum_k alpha_k * exp(-beta_k*(kappa_k - l)^2) ----
    const float scale = (float)L_ / tlen[b];
    float* phi_out = out + (size_t)B_ * V_ + (size_t)B_ * K_ + (size_t)b * (L_ + 1);
    for (int l = tid; l <= L_; l += THREADS) {
        const float fl = (float)l;
        float s = 0.f;
        #pragma unroll
        for (int k = 0; k < K_; k++) {
            float d = kappa_s[k] - fl;
            s += alpha_s[k] * __expf(-beta_s[k] * d * d);
        }
        phi_out[l] = s * scale;
    }
}

// ============================================================================
// Kernel B: w[v] = sum_{l<L} phi[l] * oh[b][l][v]   (pure HBM stream)
// Lean body -> ~28 live regs -> real 8 CTAs/SM without spills.
// ============================================================================
__global__ __launch_bounds__(THREADS, 8)
void contract_kernel(const float* __restrict__ oh,
                     float* out)
{
    const int b    = blockIdx.x;
    const int tid  = threadIdx.x;
    const int lane = tid & 31;
    const int warp = tid >> 5;

    __shared__ float  phi_s[L_];
    __shared__ float4 red[NWARP * 20];

    // phi row lives in out (written by kernel A); stride L+1=1025 is ODD, so
    // the row base is only 4-byte aligned -> SCALAR loads (L2-resident, cheap).
    const float* phi_in = out + (size_t)B_ * V_ + (size_t)B_ * K_ + (size_t)b * (L_ + 1);
    for (int i = tid; i < L_; i += THREADS) phi_s[i] = phi_in[i];
    __syncthreads();

    // One row = 80 floats = 20 float4. Lanes 0..19 fetch a whole row as
    // LDG.128; warp-strided over l, unrolled x4 with front-batched loads.
    if (lane < 20) {
        const float4* base = (const float4*)(oh + (size_t)b * L_ * V_) + lane;
        float4 acc = make_float4(0.f, 0.f, 0.f, 0.f);
        // 1024 / (8 warps * 4 unroll) = 32 iterations, no remainder
        for (int l0 = warp; l0 < L_; l0 += NWARP * 4) {
            float4 r0 = base[(size_t)(l0            ) * 20];
            float4 r1 = base[(size_t)(l0 +     NWARP) * 20];
            float4 r2 = base[(size_t)(l0 + 2 * NWARP) * 20];
            float4 r3 = base[(size_t)(l0 + 3 * NWARP) * 20];
            float p0 = phi_s[l0];
            float p1 = phi_s[l0 +     NWARP];
            float p2 = phi_s[l0 + 2 * NWARP];
            float p3 = phi_s[l0 + 3 * NWARP];
            acc.x += p0 * r0.x; acc.y += p0 * r0.y; acc.z += p0 * r0.z; acc.w += p0 * r0.w;
            acc.x += p1 * r1.x; acc.y += p1 * r1.y; acc.z += p1 * r1.z; acc.w += p1 * r1.w;
            acc.x += p2 * r2.x; acc.y += p2 * r2.y; acc.z += p2 * r2.z; acc.w += p2 * r2.w;
            acc.x += p3 * r3.x; acc.y += p3 * r3.y; acc.z += p3 * r3.z; acc.w += p3 * r3.w;
        }
        red[warp * 20 + lane] = acc;
    }
    __syncthreads();

    // final cross-warp reduction: thread v (<80) sums scalar slot v of all warps
    if (tid < V_) {
        const float* red_f = (const float*)red;
        float s = 0.f;
        #pragma unroll
        for (int w2 = 0; w2 < NWARP; w2++) s += red_f[w2 * V_ + tid];
        out[(size_t)b * V_ + tid] = s;   // w output
    }
}

extern "C" void kernel_launch(void* const* d_in, const int* in_sizes, int n_in,
                              void* d_out, int out_size)
{
    const float* x         = (const float*)d_in[0];   // [B, CELL]
    const float* kappa_old = (const float*)d_in[1];   // [B, K]
    const float* oh        = (const float*)d_in[2];   // [B, L, V]
    const float* tlen      = (const float*)d_in[3];   // [B, 1]
    const float* W         = (const float*)d_in[4];   // [3K, CELL]
    const float* bias      = (const float*)d_in[5];   // [3K]
    float* out             = (float*)d_out;           // [B*V | B*K | B*(L+1)]

    params_phi_kernel<<<B_, THREADS>>>(x, kappa_old, tlen, W, bias, out);
    contract_kernel<<<B_, THREADS>>>(oh, out);
}

// round 12
// speedup vs baseline: 1.3728x; 1.0060x over previous
#include <cuda_runtime.h>
#include <cuda_bf16.h>

// Problem constants
#define B_    2048
#define CELL_ 512
#define K_    30
#define L_    1024
#define V_    80
#define P_    90      // 3*K
#define NWARP 8
#define THREADS (NWARP*32)   // 256
#define RB    4              // batch rows per CTA in kernel A
#define TCUT  32.0f          // exp(-32) ~ 1.3e-14: truncation threshold

// ============================================================================
// Kernel A: params = exp(x@W.T + b); kappa; phi   (RB rows/CTA, W reuse x4)
// ============================================================================
__global__ __launch_bounds__(THREADS)
void params_phi_kernel(const float* __restrict__ x,
                       const float* __restrict__ kappa_old,
                       const float* __restrict__ tlen,
                       const float* __restrict__ W,
                       const float* __restrict__ bias,
                       float* __restrict__ out)
{
    const int b0   = blockIdx.x * RB;
    const int tid  = threadIdx.x;
    const int lane = tid & 31;
    const int warp = tid >> 5;

    __shared__ float xs[RB][CELL_];
    __shared__ float alpha_s[RB][K_], beta_s[RB][K_], kappa_s[RB][K_];
    __shared__ float hi_max[RB];

    // ---- load RB x-rows into smem (contiguous, vectorized) ----
    {
        const float4* xrow4 = (const float4*)(x + (size_t)b0 * CELL_);
        float4* xs4 = (float4*)&xs[0][0];
        #pragma unroll
        for (int i = tid; i < RB * CELL_ / 4; i += THREADS) xs4[i] = xrow4[i];
    }
    __syncthreads();

    // ---- params for all RB rows; each W load amortized over RB dots ----
    for (int p = warp; p < P_; p += NWARP) {
        const float4* Wr4 = (const float4*)(W + (size_t)p * CELL_);
        float s0 = 0.f, s1 = 0.f, s2 = 0.f, s3 = 0.f;
        #pragma unroll 4
        for (int c = lane; c < CELL_ / 4; c += 32) {
            float4 wv = Wr4[c];
            float4 x0 = ((const float4*)xs[0])[c];
            float4 x1 = ((const float4*)xs[1])[c];
            float4 x2 = ((const float4*)xs[2])[c];
            float4 x3 = ((const float4*)xs[3])[c];
            s0 += wv.x * x0.x + wv.y * x0.y + wv.z * x0.z + wv.w * x0.w;
            s1 += wv.x * x1.x + wv.y * x1.y + wv.z * x1.z + wv.w * x1.w;
            s2 += wv.x * x2.x + wv.y * x2.y + wv.z * x2.z + wv.w * x2.w;
            s3 += wv.x * x3.x + wv.y * x3.y + wv.z * x3.z + wv.w * x3.w;
        }
        #pragma unroll
        for (int o = 16; o; o >>= 1) {
            s0 += __shfl_xor_sync(0xffffffffu, s0, o);
            s1 += __shfl_xor_sync(0xffffffffu, s1, o);
            s2 += __shfl_xor_sync(0xffffffffu, s2, o);
            s3 += __shfl_xor_sync(0xffffffffu, s3, o);
        }
        if (lane == 0) {
            float sv[RB] = {s0, s1, s2, s3};
            #pragma unroll
            for (int r = 0; r < RB; r++) {
                float v = __expf(sv[r] + bias[p]);
                if (p < K_) {
                    alpha_s[r][p] = v;
                } else if (p < 2 * K_) {
                    beta_s[r][p - K_] = v;
                } else {
                    int kk = p - 2 * K_;
                    float kap = kappa_old[(size_t)(b0 + r) * K_ + kk] + v;
                    kappa_s[r][kk] = kap;
                    out[(size_t)B_ * V_ + (size_t)(b0 + r) * K_ + kk] = kap;
                }
            }
        }
    }
    __syncthreads();

    // ---- per-row Gaussian support bound: beyond hi_max all terms < 1.3e-14 ----
    if (tid < RB) {
        float mh = 0.f;
        #pragma unroll
        for (int k = 0; k < K_; k++) {
            float hw = sqrtf(TCUT / beta_s[tid][k]) + 1.0f;
            float hi = kappa_s[tid][k] + hw;
            mh = fmaxf(mh, hi);
        }
        hi_max[tid] = mh;
    }
    __syncthreads();

    // ---- phi[l] = scale * sum_k alpha_k * exp(-beta_k*(kappa_k - l)^2) ----
    #pragma unroll
    for (int r = 0; r < RB; r++) {
        const float scale = (float)L_ / tlen[b0 + r];
        const float mh = hi_max[r];
        float* phi_out = out + (size_t)B_ * V_ + (size_t)B_ * K_
                             + (size_t)(b0 + r) * (L_ + 1);
        for (int l = tid; l <= L_; l += THREADS) {
            const float fl = (float)l;
            if (fl > mh) {          // warp-uniform for nearly all warps
                phi_out[l] = 0.f;
            } else {
                float s = 0.f;
                #pragma unroll
                for (int k = 0; k < K_; k++) {
                    float d = kappa_s[r][k] - fl;
                    s += alpha_s[r][k] * __expf(-beta_s[r][k] * d * d);
                }
                phi_out[l] = s * scale;
            }
        }
    }
}

// ============================================================================
// Kernel B: w[v] = sum_{l<L} phi[l] * oh[b][l][v]   (pure HBM stream, 103us)
// ============================================================================
__global__ __launch_bounds__(THREADS, 8)
void contract_kernel(const float* __restrict__ oh,
                     float* out)
{
    const int b    = blockIdx.x;
    const int tid  = threadIdx.x;
    const int lane = tid & 31;
    const int warp = tid >> 5;

    __shared__ float  phi_s[L_];
    __shared__ float4 red[NWARP * 20];

    // phi row lives in out (stride L+1=1025 is odd -> scalar loads, L2-hot)
    const float* phi_in = out + (size_t)B_ * V_ + (size_t)B_ * K_ + (size_t)b * (L_ + 1);
    for (int i = tid; i < L_; i += THREADS) phi_s[i] = phi_in[i];
    __syncthreads();

    // One row = 80 floats = 20 float4. Lanes 0..19 fetch a whole row as
    // LDG.128; warp-strided over l, unrolled x4 with front-batched loads.
    if (lane < 20) {
        const float4* base = (const float4*)(oh + (size_t)b * L_ * V_) + lane;
        float4 acc = make_float4(0.f, 0.f, 0.f, 0.f);
        for (int l0 = warp; l0 < L_; l0 += NWARP * 4) {
            float4 r0 = base[(size_t)(l0            ) * 20];
            float4 r1 = base[(size_t)(l0 +     NWARP) * 20];
            float4 r2 = base[(size_t)(l0 + 2 * NWARP) * 20];
            float4 r3 = base[(size_t)(l0 + 3 * NWARP) * 20];
            float p0 = phi_s[l0];
            float p1 = phi_s[l0 +     NWARP];
            float p2 = phi_s[l0 + 2 * NWARP];
            float p3 = phi_s[l0 + 3 * NWARP];
            acc.x += p0 * r0.x; acc.y += p0 * r0.y; acc.z += p0 * r0.z; acc.w += p0 * r0.w;
            acc.x += p1 * r1.x; acc.y += p1 * r1.y; acc.z += p1 * r1.z; acc.w += p1 * r1.w;
            acc.x += p2 * r2.x; acc.y += p2 * r2.y; acc.z += p2 * r2.z; acc.w += p2 * r2.w;
            acc.x += p3 * r3.x; acc.y += p3 * r3.y; acc.z += p3 * r3.z; acc.w += p3 * r3.w;
        }
        red[warp * 20 + lane] = acc;
    }
    __syncthreads();

    if (tid < V_) {
        const float* red_f = (const float*)red;
        float s = 0.f;
        #pragma unroll
        for (int w2 = 0; w2 < NWARP; w2++) s += red_f[w2 * V_ + tid];
        out[(size_t)b * V_ + tid] = s;   // w output
    }
}

extern "C" void kernel_launch(void* const* d_in, const int* in_sizes, int n_in,
                              void* d_out, int out_size)
{
    const float* x         = (const float*)d_in[0];   // [B, CELL]
    const float* kappa_old = (const float*)d_in[1];   // [B, K]
    const float* oh        = (const float*)d_in[2];   // [B, L, V]
    const float* tlen      = (const float*)d_in[3];   // [B, 1]
    const float* W         = (const float*)d_in[4];   // [3K, CELL]
    const float* bias      = (const float*)d_in[5];   // [3K]
    float* out             = (float*)d_out;           // [B*V | B*K | B*(L+1)]

    params_phi_kernel<<<B_ / RB, THREADS>>>(x, kappa_old, tlen, W, bias, out);
    contract_kernel<<<B_, THREADS>>>(oh, out);
}

// round 13
// speedup vs baseline: 1.5562x; 1.1336x over previous
#include <cuda_runtime.h>
#include <cuda_bf16.h>

// Problem constants
#define B_    2048
#define CELL_ 512
#define K_    30
#define L_    1024
#define V_    80
#define P_    90      // 3*K
#define NWARP 8
#define THREADS (NWARP*32)   // 256
#define RB    4              // batch rows per CTA in kernel A1
#define TCUT  32.0f          // exp(-32) ~ 1.3e-14: truncation threshold

// Scratch for alpha/beta between A1 and A2 (static device arrays are allowed)
__device__ float g_alpha[B_ * K_];
__device__ float g_beta [B_ * K_];

// ============================================================================
// Kernel A1: params = exp(x@W.T + b)  -> g_alpha, g_beta, kappa -> out
// GEMM phase ONLY: lean register footprint, no phi phase sharing the alloc.
// ============================================================================
__global__ __launch_bounds__(THREADS)
void params_kernel(const float* __restrict__ x,
                   const float* __restrict__ kappa_old,
                   const float* __restrict__ W,
                   const float* __restrict__ bias,
                   float* __restrict__ out)
{
    const int b0   = blockIdx.x * RB;
    const int tid  = threadIdx.x;
    const int lane = tid & 31;
    const int warp = tid >> 5;

    __shared__ float xs[RB][CELL_];

    // ---- load RB x-rows into smem (contiguous, vectorized) ----
    {
        const float4* xrow4 = (const float4*)(x + (size_t)b0 * CELL_);
        float4* xs4 = (float4*)&xs[0][0];
        for (int i = tid; i < RB * CELL_ / 4; i += THREADS) xs4[i] = xrow4[i];
    }
    __syncthreads();

    // ---- warp w handles p = w, w+8, ...; each W load amortized over RB rows ----
    for (int p = warp; p < P_; p += NWARP) {
        const float4* Wr4 = (const float4*)(W + (size_t)p * CELL_);
        float s0 = 0.f, s1 = 0.f, s2 = 0.f, s3 = 0.f;
        #pragma unroll 4
        for (int c = lane; c < CELL_ / 4; c += 32) {
            float4 wv = Wr4[c];
            float4 x0 = ((const float4*)xs[0])[c];
            float4 x1 = ((const float4*)xs[1])[c];
            float4 x2 = ((const float4*)xs[2])[c];
            float4 x3 = ((const float4*)xs[3])[c];
            s0 += wv.x * x0.x + wv.y * x0.y + wv.z * x0.z + wv.w * x0.w;
            s1 += wv.x * x1.x + wv.y * x1.y + wv.z * x1.z + wv.w * x1.w;
            s2 += wv.x * x2.x + wv.y * x2.y + wv.z * x2.z + wv.w * x2.w;
            s3 += wv.x * x3.x + wv.y * x3.y + wv.z * x3.z + wv.w * x3.w;
        }
        #pragma unroll
        for (int o = 16; o; o >>= 1) {
            s0 += __shfl_xor_sync(0xffffffffu, s0, o);
            s1 += __shfl_xor_sync(0xffffffffu, s1, o);
            s2 += __shfl_xor_sync(0xffffffffu, s2, o);
            s3 += __shfl_xor_sync(0xffffffffu, s3, o);
        }
        if (lane == 0) {
            float sv[RB] = {s0, s1, s2, s3};
            const float bp = bias[p];
            #pragma unroll
            for (int r = 0; r < RB; r++) {
                float v = __expf(sv[r] + bp);
                if (p < K_) {
                    g_alpha[(size_t)(b0 + r) * K_ + p] = v;
                } else if (p < 2 * K_) {
                    g_beta[(size_t)(b0 + r) * K_ + (p - K_)] = v;
                } else {
                    int kk = p - 2 * K_;
                    float kap = kappa_old[(size_t)(b0 + r) * K_ + kk] + v;
                    out[(size_t)B_ * V_ + (size_t)(b0 + r) * K_ + kk] = kap;
                }
            }
        }
    }
}

// ============================================================================
// Kernel A2: phi[l] = scale * sum_k alpha_k * exp(-beta_k*(kappa_k-l)^2)
// Truncated at the Gaussian support bound; lean, one row per CTA.
// ============================================================================
__global__ __launch_bounds__(THREADS)
void phi_kernel(const float* __restrict__ tlen,
                float* __restrict__ out)
{
    const int b   = blockIdx.x;
    const int tid = threadIdx.x;

    __shared__ float alpha_s[K_], beta_s[K_], kappa_s[K_];
    __shared__ float hi_max;

    if (tid < K_) {
        alpha_s[tid] = g_alpha[(size_t)b * K_ + tid];
        beta_s[tid]  = g_beta [(size_t)b * K_ + tid];
        kappa_s[tid] = out[(size_t)B_ * V_ + (size_t)b * K_ + tid];
    }
    __syncthreads();

    if (tid < 32) {
        float hi = 0.f;
        if (tid < K_)
            hi = kappa_s[tid] + sqrtf(TCUT / beta_s[tid]) + 1.0f;
        #pragma unroll
        for (int o = 16; o; o >>= 1) hi = fmaxf(hi, __shfl_xor_sync(0xffffffffu, hi, o));
        if (tid == 0) hi_max = hi;
    }
    __syncthreads();

    const float scale = (float)L_ / tlen[b];
    const float mh = hi_max;
    float* phi_out = out + (size_t)B_ * V_ + (size_t)B_ * K_ + (size_t)b * (L_ + 1);
    for (int l = tid; l <= L_; l += THREADS) {
        const float fl = (float)l;
        if (fl > mh) {          // warp-uniform for nearly all warps
            phi_out[l] = 0.f;
        } else {
            float s = 0.f;
            #pragma unroll
            for (int k = 0; k < K_; k++) {
                float d = kappa_s[k] - fl;
                s += alpha_s[k] * __expf(-beta_s[k] * d * d);
            }
            phi_out[l] = s * scale;
        }
    }
}

// ============================================================================
// Kernel B: w[v] = sum_{l<L} phi[l] * oh[b][l][v]   (pure HBM stream, proven)
// ============================================================================
__global__ __launch_bounds__(THREADS, 8)
void contract_kernel(const float* __restrict__ oh,
                     float* out)
{
    const int b    = blockIdx.x;
    const int tid  = threadIdx.x;
    const int lane = tid & 31;
    const int warp = tid >> 5;

    __shared__ float  phi_s[L_];
    __shared__ float4 red[NWARP * 20];

    // phi row lives in out (stride L+1=1025 is odd -> scalar loads, L2-hot)
    const float* phi_in = out + (size_t)B_ * V_ + (size_t)B_ * K_ + (size_t)b * (L_ + 1);
    for (int i = tid; i < L_; i += THREADS) phi_s[i] = phi_in[i];
    __syncthreads();

    // One row = 80 floats = 20 float4. Lanes 0..19 fetch a whole row as
    // LDG.128; warp-strided over l, unrolled x4 with front-batched loads.
    if (lane < 20) {
        const float4* base = (const float4*)(oh + (size_t)b * L_ * V_) + lane;
        float4 acc = make_float4(0.f, 0.f, 0.f, 0.f);
        for (int l0 = warp; l0 < L_; l0 += NWARP * 4) {
            float4 r0 = base[(size_t)(l0            ) * 20];
            float4 r1 = base[(size_t)(l0 +     NWARP) * 20];
            float4 r2 = base[(size_t)(l0 + 2 * NWARP) * 20];
            float4 r3 = base[(size_t)(l0 + 3 * NWARP) * 20];
            float p0 = phi_s[l0];
            float p1 = phi_s[l0 +     NWARP];
            float p2 = phi_s[l0 + 2 * NWARP];
            float p3 = phi_s[l0 + 3 * NWARP];
            acc.x += p0 * r0.x; acc.y += p0 * r0.y; acc.z += p0 * r0.z; acc.w += p0 * r0.w;
            acc.x += p1 * r1.x; acc.y += p1 * r1.y; acc.z += p1 * r1.z; acc.w += p1 * r1.w;
            acc.x += p2 * r2.x; acc.y += p2 * r2.y; acc.z += p2 * r2.z; acc.w += p2 * r2.w;
            acc.x += p3 * r3.x; acc.y += p3 * r3.y; acc.z += p3 * r3.z; acc.w += p3 * r3.w;
        }
        red[warp * 20 + lane] = acc;
    }
    __syncthreads();

    if (tid < V_) {
        const float* red_f = (const float*)red;
        float s = 0.f;
        #pragma unroll
        for (int w2 = 0; w2 < NWARP; w2++) s += red_f[w2 * V_ + tid];
        out[(size_t)b * V_ + tid] = s;   // w output
    }
}

extern "C" void kernel_launch(void* const* d_in, const int* in_sizes, int n_in,
                              void* d_out, int out_size)
{
    const float* x         = (const float*)d_in[0];   // [B, CELL]
    const float* kappa_old = (const float*)d_in[1];   // [B, K]
    const float* oh        = (const float*)d_in[2];   // [B, L, V]
    const float* tlen      = (const float*)d_in[3];   // [B, 1]
    const float* W         = (const float*)d_in[4];   // [3K, CELL]
    const float* bias      = (const float*)d_in[5];   // [3K]
    float* out             = (float*)d_out;           // [B*V | B*K | B*(L+1)]

    params_kernel<<<B_ / RB, THREADS>>>(x, kappa_old, W, bias, out);
    phi_kernel<<<B_, THREADS>>>(tlen, out);
    contract_kernel<<<B_, THREADS>>>(oh, out);
}

// round 14
// speedup vs baseline: 1.6513x; 1.0611x over previous
#include <cuda_runtime.h>
#include <cuda_bf16.h>

// Problem constants
#define B_    2048
#define CELL_ 512
#define K_    30
#define L_    1024
#define V_    80
#define P_    90      // 3*K
#define NWARP 8
#define THREADS (NWARP*32)   // 256
#define RB    4              // batch rows per CTA in kernel A1
#define TCUT  32.0f          // exp(-32) ~ 1.3e-14: truncation threshold

// Scratch for alpha/beta between A1 and B (static device arrays are allowed)
__device__ float g_alpha[B_ * K_];
__device__ float g_beta [B_ * K_];

// ============================================================================
// Kernel A1: params = exp(x@W.T + b)  -> g_alpha, g_beta, kappa -> out
// 64-reg cap -> 4 CTAs/SM (47% occ) to hide L2-latency W loads + shuffles.
// ============================================================================
__global__ __launch_bounds__(THREADS, 4)
void params_kernel(const float* __restrict__ x,
                   const float* __restrict__ kappa_old,
                   const float* __restrict__ W,
                   const float* __restrict__ bias,
                   float* __restrict__ out)
{
    const int b0   = blockIdx.x * RB;
    const int tid  = threadIdx.x;
    const int lane = tid & 31;
    const int warp = tid >> 5;

    __shared__ float xs[RB][CELL_];

    // ---- load RB x-rows into smem (contiguous, vectorized) ----
    {
        const float4* xrow4 = (const float4*)(x + (size_t)b0 * CELL_);
        float4* xs4 = (float4*)&xs[0][0];
        for (int i = tid; i < RB * CELL_ / 4; i += THREADS) xs4[i] = xrow4[i];
    }
    __syncthreads();

    // ---- warp w handles p = w, w+8, ...; each W load amortized over RB rows ----
    for (int p = warp; p < P_; p += NWARP) {
        const float4* Wr4 = (const float4*)(W + (size_t)p * CELL_);
        float s0 = 0.f, s1 = 0.f, s2 = 0.f, s3 = 0.f;
        #pragma unroll
        for (int c = lane; c < CELL_ / 4; c += 32) {
            float4 wv = Wr4[c];
            float4 x0 = ((const float4*)xs[0])[c];
            float4 x1 = ((const float4*)xs[1])[c];
            float4 x2 = ((const float4*)xs[2])[c];
            float4 x3 = ((const float4*)xs[3])[c];
            s0 += wv.x * x0.x + wv.y * x0.y + wv.z * x0.z + wv.w * x0.w;
            s1 += wv.x * x1.x + wv.y * x1.y + wv.z * x1.z + wv.w * x1.w;
            s2 += wv.x * x2.x + wv.y * x2.y + wv.z * x2.z + wv.w * x2.w;
            s3 += wv.x * x3.x + wv.y * x3.y + wv.z * x3.z + wv.w * x3.w;
        }
        #pragma unroll
        for (int o = 16; o; o >>= 1) {
            s0 += __shfl_xor_sync(0xffffffffu, s0, o);
            s1 += __shfl_xor_sync(0xffffffffu, s1, o);
            s2 += __shfl_xor_sync(0xffffffffu, s2, o);
            s3 += __shfl_xor_sync(0xffffffffu, s3, o);
        }
        if (lane == 0) {
            float sv[RB] = {s0, s1, s2, s3};
            const float bp = bias[p];
            #pragma unroll
            for (int r = 0; r < RB; r++) {
                float v = __expf(sv[r] + bp);
                if (p < K_) {
                    g_alpha[(size_t)(b0 + r) * K_ + p] = v;
                } else if (p < 2 * K_) {
                    g_beta[(size_t)(b0 + r) * K_ + (p - K_)] = v;
                } else {
                    int kk = p - 2 * K_;
                    float kap = kappa_old[(size_t)(b0 + r) * K_ + kk] + v;
                    out[(size_t)B_ * V_ + (size_t)(b0 + r) * K_ + kk] = kap;
                }
            }
        }
    }
}

// ============================================================================
// Kernel B (fused): phi compute (truncated) + w contraction (HBM stream)
// ============================================================================
__global__ __launch_bounds__(THREADS, 8)
void contract_kernel(const float* __restrict__ oh,
                     const float* __restrict__ tlen,
                     float* out)
{
    const int b    = blockIdx.x;
    const int tid  = threadIdx.x;
    const int lane = tid & 31;
    const int warp = tid >> 5;

    __shared__ float  phi_s[L_];
    __shared__ float  alpha_s[K_], beta_s[K_], kappa_s[K_];
    __shared__ float  hi_max;
    __shared__ float4 red[NWARP * 20];

    // ---- fetch params (kappa was written to out by A1) ----
    if (tid < K_) {
        alpha_s[tid] = g_alpha[(size_t)b * K_ + tid];
        beta_s[tid]  = g_beta [(size_t)b * K_ + tid];
        kappa_s[tid] = out[(size_t)B_ * V_ + (size_t)b * K_ + tid];
    }
    __syncthreads();

    // ---- Gaussian support bound ----
    if (tid < 32) {
        float hi = 0.f;
        if (tid < K_)
            hi = kappa_s[tid] + sqrtf(TCUT / beta_s[tid]) + 1.0f;
        #pragma unroll
        for (int o = 16; o; o >>= 1) hi = fmaxf(hi, __shfl_xor_sync(0xffffffffu, hi, o));
        if (tid == 0) hi_max = hi;
    }
    __syncthreads();

    // ---- phi[l]: compute into smem AND write the phi output ----
    {
        const float scale = (float)L_ / tlen[b];
        const float mh = hi_max;
        float* phi_out = out + (size_t)B_ * V_ + (size_t)B_ * K_ + (size_t)b * (L_ + 1);
        for (int l = tid; l <= L_; l += THREADS) {
            const float fl = (float)l;
            float s = 0.f;
            if (fl <= mh) {     // warp-uniform for nearly all warps
                #pragma unroll 6
                for (int k = 0; k < K_; k++) {
                    float d = kappa_s[k] - fl;
                    s += alpha_s[k] * __expf(-beta_s[k] * d * d);
                }
                s *= scale;
            }
            if (l < L_) phi_s[l] = s;
            phi_out[l] = s;
        }
    }
    __syncthreads();

    // ---- w[v] = sum_{l<L} phi[l] * oh[b][l][v] ----
    // One row = 80 floats = 20 float4. Lanes 0..19 fetch a whole row as
    // LDG.128; warp-strided over l, unrolled x4 with front-batched loads.
    if (lane < 20) {
        const float4* base = (const float4*)(oh + (size_t)b * L_ * V_) + lane;
        float4 acc = make_float4(0.f, 0.f, 0.f, 0.f);
        for (int l0 = warp; l0 < L_; l0 += NWARP * 4) {
            float4 r0 = base[(size_t)(l0            ) * 20];
            float4 r1 = base[(size_t)(l0 +     NWARP) * 20];
            float4 r2 = base[(size_t)(l0 + 2 * NWARP) * 20];
            float4 r3 = base[(size_t)(l0 + 3 * NWARP) * 20];
            float p0 = phi_s[l0];
            float p1 = phi_s[l0 +     NWARP];
            float p2 = phi_s[l0 + 2 * NWARP];
            float p3 = phi_s[l0 + 3 * NWARP];
            acc.x += p0 * r0.x; acc.y += p0 * r0.y; acc.z += p0 * r0.z; acc.w += p0 * r0.w;
            acc.x += p1 * r1.x; acc.y += p1 * r1.y; acc.z += p1 * r1.z; acc.w += p1 * r1.w;
            acc.x += p2 * r2.x; acc.y += p2 * r2.y; acc.z += p2 * r2.z; acc.w += p2 * r2.w;
            acc.x += p3 * r3.x; acc.y += p3 * r3.y; acc.z += p3 * r3.z; acc.w += p3 * r3.w;
        }
        red[warp * 20 + lane] = acc;
    }
    __syncthreads();

    if (tid < V_) {
        const float* red_f = (const float*)red;
        float s = 0.f;
        #pragma unroll
        for (int w2 = 0; w2 < NWARP; w2++) s += red_f[w2 * V_ + tid];
        out[(size_t)b * V_ + tid] = s;   // w output
    }
}

extern "C" void kernel_launch(void* const* d_in, const int* in_sizes, int n_in,
                              void* d_out, int out_size)
{
    const float* x         = (const float*)d_in[0];   // [B, CELL]
    const float* kappa_old = (const float*)d_in[1];   // [B, K]
    const float* oh        = (const float*)d_in[2];   // [B, L, V]
    const float* tlen      = (const float*)d_in[3];   // [B, 1]
    const float* W         = (const float*)d_in[4];   // [3K, CELL]
    const float* bias      = (const float*)d_in[5];   // [3K]
    float* out             = (float*)d_out;           // [B*V | B*K | B*(L+1)]

    params_kernel<<<B_ / RB, THREADS>>>(x, kappa_old, W, bias, out);
    contract_kernel<<<B_, THREADS>>>(oh, tlen, out);
}